// round 1
// baseline (speedup 1.0000x reference)
#include <cuda_runtime.h>
#include <cuda_bf16.h>
#include <math.h>

// Problem constants
#define BATCH 2
#define SEQ   2048
#define DMODEL 1024
#define NHEAD 16
#define DK    64
#define MROWS (BATCH*SEQ)   // 4096

// ---------------- scratch (allocation-free rule: __device__ globals) ----------
__device__ float g_Q[MROWS * DMODEL];   // (B*H, S, DK) layout
__device__ float g_K[MROWS * DMODEL];
__device__ float g_V[MROWS * DMODEL];
__device__ float g_A[MROWS * DMODEL];   // attention output, merged (B,S,D)

// ---------------- SGEMM: C[m,n] = sum_k A[m,k] * W[n,k] + bias[n] -------------
// A: [M,1024] row-major, W: [1024,1024] row-major (so this is x @ W^T).
// split==1: scatter into split-head layout ((b*H+h)*S + s)*DK + dk
// split==0: plain row-major [M,1024]
#define GBM 128
#define GBN 128
#define GBK 16

__global__ __launch_bounds__(256) void sgemm_nt_kernel(
    const float* __restrict__ A, const float* __restrict__ W,
    const float* __restrict__ bias, float* __restrict__ C, int split)
{
    __shared__ float As[GBK][GBM];
    __shared__ float Ws[GBK][GBN];

    const int tid = threadIdx.x;
    const int tx = tid & 15;    // n-direction
    const int ty = tid >> 4;    // m-direction
    const int m0 = blockIdx.y * GBM;
    const int n0 = blockIdx.x * GBN;

    // loading indices: tile is 128 rows x 16 k = 512 float4; 2 per thread
    const int lrow = tid >> 2;  // 0..63
    const int lc4  = tid & 3;   // 0..3 (float4 along k)

    float acc[8][8];
#pragma unroll
    for (int i = 0; i < 8; i++)
#pragma unroll
        for (int j = 0; j < 8; j++) acc[i][j] = 0.f;

    for (int k0 = 0; k0 < DMODEL; k0 += GBK) {
#pragma unroll
        for (int rep = 0; rep < 2; rep++) {
            int row = lrow + rep * 64;
            float4 av = *(const float4*)&A[(size_t)(m0 + row) * DMODEL + k0 + lc4 * 4];
            As[lc4*4+0][row] = av.x; As[lc4*4+1][row] = av.y;
            As[lc4*4+2][row] = av.z; As[lc4*4+3][row] = av.w;
            float4 wv = *(const float4*)&W[(size_t)(n0 + row) * DMODEL + k0 + lc4 * 4];
            Ws[lc4*4+0][row] = wv.x; Ws[lc4*4+1][row] = wv.y;
            Ws[lc4*4+2][row] = wv.z; Ws[lc4*4+3][row] = wv.w;
        }
        __syncthreads();

#pragma unroll
        for (int k = 0; k < GBK; k++) {
            float af[8], bf[8];
            *(float4*)&af[0] = *(const float4*)&As[k][ty*8];
            *(float4*)&af[4] = *(const float4*)&As[k][ty*8+4];
            *(float4*)&bf[0] = *(const float4*)&Ws[k][tx*8];
            *(float4*)&bf[4] = *(const float4*)&Ws[k][tx*8+4];
#pragma unroll
            for (int i = 0; i < 8; i++)
#pragma unroll
                for (int j = 0; j < 8; j++)
                    acc[i][j] = fmaf(af[i], bf[j], acc[i][j]);
        }
        __syncthreads();
    }

    // epilogue
#pragma unroll
    for (int i = 0; i < 8; i++) {
        int m = m0 + ty * 8 + i;
        int b = m >> 11;          // /SEQ (2048)
        int s = m & 2047;
#pragma unroll
        for (int jj = 0; jj < 8; jj += 4) {
            int n = n0 + tx * 8 + jj;
            float4 bv = *(const float4*)&bias[n];
            float4 v;
            v.x = acc[i][jj+0] + bv.x;
            v.y = acc[i][jj+1] + bv.y;
            v.z = acc[i][jj+2] + bv.z;
            v.w = acc[i][jj+3] + bv.w;
            if (split) {
                int h  = n >> 6;      // /DK
                int dk = n & 63;
                *(float4*)&C[(((size_t)(b * NHEAD + h)) * SEQ + s) * DK + dk] = v;
            } else {
                *(float4*)&C[(size_t)m * DMODEL + n] = v;
            }
        }
    }
}

// ---------------- Flash attention (causal), fp32 ------------------------------
// Q,K,V: (B*H, S, DK) row-major.  Out: merged (B, S, D).
// Block: 256 threads (8 warps). Each block: 64 query rows of one (b,h).
// Warp w owns rows w*8..w*8+7. Lane owns keys {lane, lane+32} in QK phase and
// dk {lane, lane+32} in PV phase.
__global__ __launch_bounds__(256) void flash_attn_kernel(
    const float* __restrict__ Q, const float* __restrict__ K,
    const float* __restrict__ V, float* __restrict__ Out)
{
    extern __shared__ float sm[];
    float* Qs = sm;                 // [64][64]
    float* Ks = Qs + 64 * 64;       // [64][68]  (pad 4 -> conflict-free per-lane rows)
    float* Vs = Ks + 64 * 68;       // [64][64]
    float* Ps = Vs + 64 * 64;       // [64][64]  (warp w rows w*8..w*8+7)

    const int qi  = blockIdx.x;     // query block (64 rows)
    const int bh  = blockIdx.y;     // b*H + h
    const int tid = threadIdx.x;
    const int w    = tid >> 5;
    const int lane = tid & 31;

    // load Q tile (64x64 = 1024 float4, 4 per thread)
    const float* Qg = Q + ((size_t)bh * SEQ + qi * 64) * DK;
#pragma unroll
    for (int rep = 0; rep < 4; rep++) {
        int lin = tid + rep * 256;
        int row = lin >> 4, c4 = lin & 15;
        ((float4*)&Qs[row * 64])[c4] = ((const float4*)&Qg[row * 64])[c4];
    }

    float m_i[8], l_i[8], acc0[8], acc1[8];
#pragma unroll
    for (int r = 0; r < 8; r++) { m_i[r] = -1e30f; l_i[r] = 0.f; acc0[r] = 0.f; acc1[r] = 0.f; }

    for (int jb = 0; jb <= qi; jb++) {
        __syncthreads();   // previous iter's smem reads done (also covers Q load on iter 0)
        const float* Kg = K + ((size_t)bh * SEQ + jb * 64) * DK;
        const float* Vg = V + ((size_t)bh * SEQ + jb * 64) * DK;
#pragma unroll
        for (int rep = 0; rep < 4; rep++) {
            int lin = tid + rep * 256;
            int row = lin >> 4, c4 = lin & 15;
            ((float4*)&Ks[row * 68])[c4] = ((const float4*)&Kg[row * 64])[c4];
            ((float4*)&Vs[row * 64])[c4] = ((const float4*)&Vg[row * 64])[c4];
        }
        __syncthreads();

        // ---- QK^T for this warp's 8 rows; lane handles keys lane, lane+32 ----
        float s0[8], s1[8];
#pragma unroll
        for (int r = 0; r < 8; r++) { s0[r] = 0.f; s1[r] = 0.f; }
        const float4* k0p = (const float4*)&Ks[lane * 68];
        const float4* k1p = (const float4*)&Ks[(lane + 32) * 68];
        const float4* qsp = (const float4*)&Qs[w * 8 * 64];
#pragma unroll
        for (int d4 = 0; d4 < 16; d4++) {
            float4 ka = k0p[d4];
            float4 kb = k1p[d4];
#pragma unroll
            for (int r = 0; r < 8; r++) {
                float4 qv = qsp[r * 16 + d4];
                s0[r] = fmaf(qv.x, ka.x, fmaf(qv.y, ka.y, fmaf(qv.z, ka.z, fmaf(qv.w, ka.w, s0[r]))));
                s1[r] = fmaf(qv.x, kb.x, fmaf(qv.y, kb.y, fmaf(qv.z, kb.z, fmaf(qv.w, kb.w, s1[r]))));
            }
        }

        // ---- online softmax ----
        const bool diag = (jb == qi);
#pragma unroll
        for (int r = 0; r < 8; r++) {
            float v0 = s0[r] * 0.125f;   // 1/sqrt(64)
            float v1 = s1[r] * 0.125f;
            if (diag) {
                int qrow = w * 8 + r;
                if (lane > qrow)      v0 = -INFINITY;
                if (lane + 32 > qrow) v1 = -INFINITY;
            }
            float mx = fmaxf(v0, v1);
#pragma unroll
            for (int off = 16; off > 0; off >>= 1)
                mx = fmaxf(mx, __shfl_xor_sync(0xffffffffu, mx, off));
            float mnew = fmaxf(m_i[r], mx);
            float p0 = __expf(v0 - mnew);
            float p1 = __expf(v1 - mnew);
            float ps = p0 + p1;
#pragma unroll
            for (int off = 16; off > 0; off >>= 1)
                ps += __shfl_xor_sync(0xffffffffu, ps, off);
            float alpha = __expf(m_i[r] - mnew);
            l_i[r] = l_i[r] * alpha + ps;
            m_i[r] = mnew;
            acc0[r] *= alpha;
            acc1[r] *= alpha;
            Ps[(w * 8 + r) * 64 + lane]      = p0;
            Ps[(w * 8 + r) * 64 + lane + 32] = p1;
        }
        __syncwarp();

        // ---- P @ V ; lane owns dk = lane, lane+32 ----
#pragma unroll 4
        for (int key = 0; key < 64; key++) {
            float vv0 = Vs[key * 64 + lane];
            float vv1 = Vs[key * 64 + lane + 32];
#pragma unroll
            for (int r = 0; r < 8; r++) {
                float p = Ps[(w * 8 + r) * 64 + key];
                acc0[r] = fmaf(p, vv0, acc0[r]);
                acc1[r] = fmaf(p, vv1, acc1[r]);
            }
        }
    }

    // ---- write merged (B,S,D): d = h*64 + dk ----
    const int b = bh >> 4;       // /NHEAD
    const int h = bh & 15;
#pragma unroll
    for (int r = 0; r < 8; r++) {
        int srow = qi * 64 + w * 8 + r;
        float inv = 1.f / l_i[r];
        size_t base = ((size_t)(b * SEQ + srow)) * DMODEL + h * DK;
        Out[base + lane]      = acc0[r] * inv;
        Out[base + lane + 32] = acc1[r] * inv;
    }
}

// ---------------- launch ------------------------------------------------------
extern "C" void kernel_launch(void* const* d_in, const int* in_sizes, int n_in,
                              void* d_out, int out_size)
{
    const float* query = (const float*)d_in[0];
    const float* key   = (const float*)d_in[1];
    const float* value = (const float*)d_in[2];
    // d_in[3] = mask (causal triu, fixed by problem definition) -> implemented analytically
    const float* Wq = (const float*)d_in[4];
    const float* bq = (const float*)d_in[5];
    const float* Wk = (const float*)d_in[6];
    const float* bk = (const float*)d_in[7];
    const float* Wv = (const float*)d_in[8];
    const float* bv = (const float*)d_in[9];
    const float* Wo = (const float*)d_in[10];
    const float* bo = (const float*)d_in[11];
    float* out = (float*)d_out;

    float *pQ, *pK, *pV, *pA;
    cudaGetSymbolAddress((void**)&pQ, g_Q);
    cudaGetSymbolAddress((void**)&pK, g_K);
    cudaGetSymbolAddress((void**)&pV, g_V);
    cudaGetSymbolAddress((void**)&pA, g_A);

    dim3 ggrid(DMODEL / GBN, MROWS / GBM);   // (8, 32)

    sgemm_nt_kernel<<<ggrid, 256>>>(query, Wq, bq, pQ, 1);
    sgemm_nt_kernel<<<ggrid, 256>>>(key,   Wk, bk, pK, 1);
    sgemm_nt_kernel<<<ggrid, 256>>>(value, Wv, bv, pV, 1);

    const int smem_bytes = (64*64 + 64*68 + 64*64 + 64*64) * (int)sizeof(float); // 66560
    cudaFuncSetAttribute(flash_attn_kernel,
                         cudaFuncAttributeMaxDynamicSharedMemorySize, smem_bytes);
    dim3 agrid(SEQ / 64, BATCH * NHEAD);     // (32, 32)
    flash_attn_kernel<<<agrid, 256, smem_bytes>>>(pQ, pK, pV, pA);

    sgemm_nt_kernel<<<ggrid, 256>>>(pA, Wo, bo, out, 0);
}

// round 3
// speedup vs baseline: 1.6128x; 1.6128x over previous
#include <cuda_runtime.h>
#include <cuda_bf16.h>
#include <math.h>
#include <stdint.h>

// Problem constants
#define BATCH 2
#define SEQ   2048
#define DMODEL 1024
#define NHEAD 16
#define DK    64
#define MROWS (BATCH*SEQ)   // 4096

// ---------------- scratch (allocation-free rule: __device__ globals) ----------
__device__ float g_Q[MROWS * DMODEL];   // (B*H, S, DK) layout
__device__ float g_K[MROWS * DMODEL];
__device__ float g_V[MROWS * DMODEL];
__device__ float g_A[MROWS * DMODEL];   // attention output, merged (B,S,D)

// =============================================================================
// tf32 tensor-core GEMM: C[m,n] = sum_k A[m,k] * W[n,k] + bias[n]
// A: [M,1024] row-major, W: [1024,1024] row-major  ->  C = A @ W^T
// split==1: scatter into split-head layout ((b*H+h)*S + s)*DK + dk
// split==0: plain row-major [M,1024]
// Block 128x128, K-tile 32. 256 thr = 8 warps; warp tile 64x32 (warp grid 2x4).
// mma.sync.aligned.m16n8k8.row.col.f32.tf32.tf32.f32
// =============================================================================
#define TBM 128
#define TBN 128
#define TBK 32
#define LDPAD 4   // smem row stride = 36 floats -> conflict-free frag loads

__device__ __forceinline__ float to_tf32(float x) {
    float r;
    asm("cvt.rna.tf32.f32 %0, %1;" : "=f"(r) : "f"(x));
    return r;
}

__device__ __forceinline__ void mma_tf32(float* c, const uint32_t* a, const uint32_t* b) {
    asm volatile(
        "mma.sync.aligned.m16n8k8.row.col.f32.tf32.tf32.f32 "
        "{%0,%1,%2,%3}, {%4,%5,%6,%7}, {%8,%9}, {%0,%1,%2,%3};"
        : "+f"(c[0]), "+f"(c[1]), "+f"(c[2]), "+f"(c[3])
        : "r"(a[0]), "r"(a[1]), "r"(a[2]), "r"(a[3]), "r"(b[0]), "r"(b[1]));
}

__global__ __launch_bounds__(256, 1) void gemm_tf32_kernel(
    const float* __restrict__ A, const float* __restrict__ W,
    const float* __restrict__ bias, float* __restrict__ C, int split)
{
    __shared__ float As[TBM][TBK + LDPAD];   // [m][k], stride 36
    __shared__ float Bs[TBN][TBK + LDPAD];   // [n][k], stride 36

    const int tid  = threadIdx.x;
    const int wid  = tid >> 5;
    const int lane = tid & 31;
    const int wm   = wid & 1;        // 0..1  (m direction, 64 rows each)
    const int wn   = wid >> 1;       // 0..3  (n direction, 32 cols each)
    const int g    = lane >> 2;      // groupID 0..7
    const int t4   = lane & 3;       // threadID_in_group 0..3

    const int m0 = blockIdx.y * TBM;
    const int n0 = blockIdx.x * TBN;

    // global->smem mapping: thread loads 4 float4 from A and 4 from B per K-tile
    const int c4   = tid & 7;        // k-float4 index 0..7 (k = c4*4)
    const int row0 = tid >> 3;       // 0..31; rows row0 + 32*rep

    float acc[4][4][4];
#pragma unroll
    for (int mt = 0; mt < 4; mt++)
#pragma unroll
        for (int nt = 0; nt < 4; nt++)
#pragma unroll
            for (int i = 0; i < 4; i++) acc[mt][nt][i] = 0.f;

    float4 ra[4], rb[4];
    // prefetch k0 = 0
#pragma unroll
    for (int rep = 0; rep < 4; rep++) {
        ra[rep] = *(const float4*)&A[(size_t)(m0 + row0 + 32 * rep) * DMODEL + c4 * 4];
        rb[rep] = *(const float4*)&W[(size_t)(n0 + row0 + 32 * rep) * DMODEL + c4 * 4];
    }

    for (int k0 = 0; k0 < DMODEL; k0 += TBK) {
        // store staged tile (with RNA tf32 rounding)
#pragma unroll
        for (int rep = 0; rep < 4; rep++) {
            float4 va = ra[rep], vb = rb[rep];
            float4 ta, tb;
            ta.x = to_tf32(va.x); ta.y = to_tf32(va.y); ta.z = to_tf32(va.z); ta.w = to_tf32(va.w);
            tb.x = to_tf32(vb.x); tb.y = to_tf32(vb.y); tb.z = to_tf32(vb.z); tb.w = to_tf32(vb.w);
            *(float4*)&As[row0 + 32 * rep][c4 * 4] = ta;
            *(float4*)&Bs[row0 + 32 * rep][c4 * 4] = tb;
        }
        __syncthreads();

        // prefetch next K-tile while mma runs
        if (k0 + TBK < DMODEL) {
#pragma unroll
            for (int rep = 0; rep < 4; rep++) {
                ra[rep] = *(const float4*)&A[(size_t)(m0 + row0 + 32 * rep) * DMODEL + k0 + TBK + c4 * 4];
                rb[rep] = *(const float4*)&W[(size_t)(n0 + row0 + 32 * rep) * DMODEL + k0 + TBK + c4 * 4];
            }
        }

        // 4 k-steps of 8
#pragma unroll
        for (int ks = 0; ks < 4; ks++) {
            const int kk = ks * 8;
            uint32_t af[4][4];
#pragma unroll
            for (int mt = 0; mt < 4; mt++) {
                const int mr = wm * 64 + mt * 16;
                af[mt][0] = __float_as_uint(As[mr + g    ][kk + t4    ]);
                af[mt][1] = __float_as_uint(As[mr + g + 8][kk + t4    ]);
                af[mt][2] = __float_as_uint(As[mr + g    ][kk + t4 + 4]);
                af[mt][3] = __float_as_uint(As[mr + g + 8][kk + t4 + 4]);
            }
            uint32_t bf[4][2];
#pragma unroll
            for (int nt = 0; nt < 4; nt++) {
                const int nc = wn * 32 + nt * 8;
                bf[nt][0] = __float_as_uint(Bs[nc + g][kk + t4    ]);
                bf[nt][1] = __float_as_uint(Bs[nc + g][kk + t4 + 4]);
            }
#pragma unroll
            for (int mt = 0; mt < 4; mt++)
#pragma unroll
                for (int nt = 0; nt < 4; nt++)
                    mma_tf32(acc[mt][nt], af[mt], bf[nt]);
        }
        __syncthreads();
    }

    // epilogue: c0:(g, 2t4) c1:(g, 2t4+1) c2:(g+8, 2t4) c3:(g+8, 2t4+1)
#pragma unroll
    for (int mt = 0; mt < 4; mt++) {
#pragma unroll
        for (int nt = 0; nt < 4; nt++) {
            const int n = n0 + wn * 32 + nt * 8 + t4 * 2;
            const float2 bv = *(const float2*)&bias[n];
#pragma unroll
            for (int half = 0; half < 2; half++) {
                const int m = m0 + wm * 64 + mt * 16 + g + half * 8;
                float2 v;
                v.x = acc[mt][nt][half * 2 + 0] + bv.x;
                v.y = acc[mt][nt][half * 2 + 1] + bv.y;
                if (split) {
                    const int b = m >> 11, s = m & 2047;
                    const int h = n >> 6,  dk = n & 63;
                    *(float2*)&C[(((size_t)(b * NHEAD + h)) * SEQ + s) * DK + dk] = v;
                } else {
                    *(float2*)&C[(size_t)m * DMODEL + n] = v;
                }
            }
        }
    }
}

// =============================================================================
// Flash attention (causal), fp32, P stored transposed for vectorized PV reads
// Q,K,V: (B*H, S, DK) row-major.  Out: merged (B, S, D).
// 256 threads (8 warps); block = 64 query rows of one (b,h); warp w owns rows
// w*8..w*8+7; lane owns keys {lane, lane+32} (QK) / dk {lane, lane+32} (PV).
// =============================================================================
#define PS_STRIDE 68   // [key][row] layout; 68*4B=272B rows -> 16B-aligned float4

__global__ __launch_bounds__(256) void flash_attn_kernel(
    const float* __restrict__ Q, const float* __restrict__ K,
    const float* __restrict__ V, float* __restrict__ Out)
{
    extern __shared__ float sm[];
    float* Qs = sm;                     // [64][64]
    float* Ks = Qs + 64 * 64;           // [64][68]
    float* Vs = Ks + 64 * 68;           // [64][64]
    float* Ps = Vs + 64 * 64;           // [64 keys][68]  transposed: [key][row]

    const int qi  = blockIdx.x;
    const int bh  = blockIdx.y;
    const int tid = threadIdx.x;
    const int w    = tid >> 5;
    const int lane = tid & 31;

    const float* Qg = Q + ((size_t)bh * SEQ + qi * 64) * DK;
#pragma unroll
    for (int rep = 0; rep < 4; rep++) {
        int lin = tid + rep * 256;
        int row = lin >> 4, c4 = lin & 15;
        ((float4*)&Qs[row * 64])[c4] = ((const float4*)&Qg[row * 64])[c4];
    }

    float m_i[8], l_i[8], acc0[8], acc1[8];
#pragma unroll
    for (int r = 0; r < 8; r++) { m_i[r] = -1e30f; l_i[r] = 0.f; acc0[r] = 0.f; acc1[r] = 0.f; }

    for (int jb = 0; jb <= qi; jb++) {
        __syncthreads();   // prev iter's smem reads done (covers Q load on iter 0)
        const float* Kg = K + ((size_t)bh * SEQ + jb * 64) * DK;
        const float* Vg = V + ((size_t)bh * SEQ + jb * 64) * DK;
#pragma unroll
        for (int rep = 0; rep < 4; rep++) {
            int lin = tid + rep * 256;
            int row = lin >> 4, c4 = lin & 15;
            ((float4*)&Ks[row * 68])[c4] = ((const float4*)&Kg[row * 64])[c4];
            ((float4*)&Vs[row * 64])[c4] = ((const float4*)&Vg[row * 64])[c4];
        }
        __syncthreads();

        // ---- QK^T: warp's 8 rows; lane handles keys lane, lane+32 ----
        float s0[8], s1[8];
#pragma unroll
        for (int r = 0; r < 8; r++) { s0[r] = 0.f; s1[r] = 0.f; }
        const float4* k0p = (const float4*)&Ks[lane * 68];
        const float4* k1p = (const float4*)&Ks[(lane + 32) * 68];
        const float4* qsp = (const float4*)&Qs[w * 8 * 64];
#pragma unroll
        for (int d4 = 0; d4 < 16; d4++) {
            float4 ka = k0p[d4];
            float4 kb = k1p[d4];
#pragma unroll
            for (int r = 0; r < 8; r++) {
                float4 qv = qsp[r * 16 + d4];
                s0[r] = fmaf(qv.x, ka.x, fmaf(qv.y, ka.y, fmaf(qv.z, ka.z, fmaf(qv.w, ka.w, s0[r]))));
                s1[r] = fmaf(qv.x, kb.x, fmaf(qv.y, kb.y, fmaf(qv.z, kb.z, fmaf(qv.w, kb.w, s1[r]))));
            }
        }

        // ---- online softmax; store P transposed [key][row] ----
        const bool diag = (jb == qi);
#pragma unroll
        for (int r = 0; r < 8; r++) {
            float v0 = s0[r] * 0.125f;   // 1/sqrt(64)
            float v1 = s1[r] * 0.125f;
            if (diag) {
                int qrow = w * 8 + r;
                if (lane > qrow)      v0 = -INFINITY;
                if (lane + 32 > qrow) v1 = -INFINITY;
            }
            float mx = fmaxf(v0, v1);
#pragma unroll
            for (int off = 16; off > 0; off >>= 1)
                mx = fmaxf(mx, __shfl_xor_sync(0xffffffffu, mx, off));
            float mnew = fmaxf(m_i[r], mx);
            float p0 = __expf(v0 - mnew);
            float p1 = __expf(v1 - mnew);
            float ps = p0 + p1;
#pragma unroll
            for (int off = 16; off > 0; off >>= 1)
                ps += __shfl_xor_sync(0xffffffffu, ps, off);
            float alpha = __expf(m_i[r] - mnew);
            l_i[r] = l_i[r] * alpha + ps;
            m_i[r] = mnew;
            acc0[r] *= alpha;
            acc1[r] *= alpha;
            Ps[lane * PS_STRIDE        + w * 8 + r] = p0;
            Ps[(lane + 32) * PS_STRIDE + w * 8 + r] = p1;
        }
        __syncwarp();

        // ---- P @ V ; lane owns dk = lane, lane+32; P via float4 broadcast ----
#pragma unroll 4
        for (int key = 0; key < 64; key++) {
            float4 pa = *(const float4*)&Ps[key * PS_STRIDE + w * 8];
            float4 pb = *(const float4*)&Ps[key * PS_STRIDE + w * 8 + 4];
            float vv0 = Vs[key * 64 + lane];
            float vv1 = Vs[key * 64 + lane + 32];
            acc0[0] = fmaf(pa.x, vv0, acc0[0]);  acc1[0] = fmaf(pa.x, vv1, acc1[0]);
            acc0[1] = fmaf(pa.y, vv0, acc0[1]);  acc1[1] = fmaf(pa.y, vv1, acc1[1]);
            acc0[2] = fmaf(pa.z, vv0, acc0[2]);  acc1[2] = fmaf(pa.z, vv1, acc1[2]);
            acc0[3] = fmaf(pa.w, vv0, acc0[3]);  acc1[3] = fmaf(pa.w, vv1, acc1[3]);
            acc0[4] = fmaf(pb.x, vv0, acc0[4]);  acc1[4] = fmaf(pb.x, vv1, acc1[4]);
            acc0[5] = fmaf(pb.y, vv0, acc0[5]);  acc1[5] = fmaf(pb.y, vv1, acc1[5]);
            acc0[6] = fmaf(pb.z, vv0, acc0[6]);  acc1[6] = fmaf(pb.z, vv1, acc1[6]);
            acc0[7] = fmaf(pb.w, vv0, acc0[7]);  acc1[7] = fmaf(pb.w, vv1, acc1[7]);
        }
    }

    // ---- write merged (B,S,D): d = h*64 + dk ----
    const int b = bh >> 4;
    const int h = bh & 15;
#pragma unroll
    for (int r = 0; r < 8; r++) {
        int srow = qi * 64 + w * 8 + r;
        float inv = 1.f / l_i[r];
        size_t base = ((size_t)(b * SEQ + srow)) * DMODEL + h * DK;
        Out[base + lane]      = acc0[r] * inv;
        Out[base + lane + 32] = acc1[r] * inv;
    }
}

// ---------------- launch ------------------------------------------------------
extern "C" void kernel_launch(void* const* d_in, const int* in_sizes, int n_in,
                              void* d_out, int out_size)
{
    const float* query = (const float*)d_in[0];
    const float* key   = (const float*)d_in[1];
    const float* value = (const float*)d_in[2];
    // d_in[3] = mask (causal triu, fixed by problem definition) -> analytic
    const float* Wq = (const float*)d_in[4];
    const float* bq = (const float*)d_in[5];
    const float* Wk = (const float*)d_in[6];
    const float* bk = (const float*)d_in[7];
    const float* Wv = (const float*)d_in[8];
    const float* bv = (const float*)d_in[9];
    const float* Wo = (const float*)d_in[10];
    const float* bo = (const float*)d_in[11];
    float* out = (float*)d_out;

    float *pQ, *pK, *pV, *pA;
    cudaGetSymbolAddress((void**)&pQ, g_Q);
    cudaGetSymbolAddress((void**)&pK, g_K);
    cudaGetSymbolAddress((void**)&pV, g_V);
    cudaGetSymbolAddress((void**)&pA, g_A);

    dim3 ggrid(DMODEL / TBN, MROWS / TBM);   // (8, 32)

    gemm_tf32_kernel<<<ggrid, 256>>>(query, Wq, bq, pQ, 1);
    gemm_tf32_kernel<<<ggrid, 256>>>(key,   Wk, bk, pK, 1);
    gemm_tf32_kernel<<<ggrid, 256>>>(value, Wv, bv, pV, 1);

    const int smem_bytes = (64*64 + 64*68 + 64*64 + 64*68) * (int)sizeof(float); // 67584
    cudaFuncSetAttribute(flash_attn_kernel,
                         cudaFuncAttributeMaxDynamicSharedMemorySize, smem_bytes);
    dim3 agrid(SEQ / 64, BATCH * NHEAD);     // (32, 32)
    flash_attn_kernel<<<agrid, 256, smem_bytes>>>(pQ, pK, pV, pA);

    gemm_tf32_kernel<<<ggrid, 256>>>(pA, Wo, bo, out, 0);
}

// round 4
// speedup vs baseline: 3.0485x; 1.8902x over previous
#include <cuda_runtime.h>
#include <cuda_bf16.h>
#include <math.h>
#include <stdint.h>

// Problem constants
#define BATCH 2
#define SEQ   2048
#define DMODEL 1024
#define NHEAD 16
#define DK    64
#define MROWS (BATCH*SEQ)   // 4096

// ---------------- scratch (allocation-free rule: __device__ globals) ----------
__device__ float g_Q[MROWS * DMODEL];   // (B*H, S, DK) layout
__device__ float g_K[MROWS * DMODEL];
__device__ float g_V[MROWS * DMODEL];
__device__ float g_A[MROWS * DMODEL];   // attention output, merged (B,S,D)

// =============================================================================
// tf32 helpers
// =============================================================================
__device__ __forceinline__ float to_tf32(float x) {
    float r;
    asm("cvt.rna.tf32.f32 %0, %1;" : "=f"(r) : "f"(x));
    return r;
}

__device__ __forceinline__ void mma_tf32(float* c, const uint32_t* a, const uint32_t* b) {
    asm volatile(
        "mma.sync.aligned.m16n8k8.row.col.f32.tf32.tf32.f32 "
        "{%0,%1,%2,%3}, {%4,%5,%6,%7}, {%8,%9}, {%0,%1,%2,%3};"
        : "+f"(c[0]), "+f"(c[1]), "+f"(c[2]), "+f"(c[3])
        : "r"(a[0]), "r"(a[1]), "r"(a[2]), "r"(a[3]), "r"(b[0]), "r"(b[1]));
}

// =============================================================================
// tf32 GEMM core: C[m,n] = sum_k A[m,k] * W[n,k] + bias[n]
// Block 128x128, K-tile 32, 8 warps, warp tile 64x32.
// =============================================================================
#define TBM 128
#define TBN 128
#define TBK 32
#define LDPAD 4   // smem row stride = 36 floats

__device__ __forceinline__ void gemm_core(
    const float* __restrict__ A, const float* __restrict__ W,
    const float* __restrict__ bias, float* __restrict__ C, int split,
    float (*As)[TBK + LDPAD], float (*Bs)[TBK + LDPAD])
{
    const int tid  = threadIdx.x;
    const int wid  = tid >> 5;
    const int lane = tid & 31;
    const int wm   = wid & 1;
    const int wn   = wid >> 1;
    const int g    = lane >> 2;
    const int t4   = lane & 3;

    const int m0 = blockIdx.y * TBM;
    const int n0 = blockIdx.x * TBN;

    const int c4   = tid & 7;
    const int row0 = tid >> 3;

    float acc[4][4][4];
#pragma unroll
    for (int mt = 0; mt < 4; mt++)
#pragma unroll
        for (int nt = 0; nt < 4; nt++)
#pragma unroll
            for (int i = 0; i < 4; i++) acc[mt][nt][i] = 0.f;

    float4 ra[4], rb[4];
#pragma unroll
    for (int rep = 0; rep < 4; rep++) {
        ra[rep] = *(const float4*)&A[(size_t)(m0 + row0 + 32 * rep) * DMODEL + c4 * 4];
        rb[rep] = *(const float4*)&W[(size_t)(n0 + row0 + 32 * rep) * DMODEL + c4 * 4];
    }

    for (int k0 = 0; k0 < DMODEL; k0 += TBK) {
#pragma unroll
        for (int rep = 0; rep < 4; rep++) {
            float4 va = ra[rep], vb = rb[rep];
            float4 ta, tb;
            ta.x = to_tf32(va.x); ta.y = to_tf32(va.y); ta.z = to_tf32(va.z); ta.w = to_tf32(va.w);
            tb.x = to_tf32(vb.x); tb.y = to_tf32(vb.y); tb.z = to_tf32(vb.z); tb.w = to_tf32(vb.w);
            *(float4*)&As[row0 + 32 * rep][c4 * 4] = ta;
            *(float4*)&Bs[row0 + 32 * rep][c4 * 4] = tb;
        }
        __syncthreads();

        if (k0 + TBK < DMODEL) {
#pragma unroll
            for (int rep = 0; rep < 4; rep++) {
                ra[rep] = *(const float4*)&A[(size_t)(m0 + row0 + 32 * rep) * DMODEL + k0 + TBK + c4 * 4];
                rb[rep] = *(const float4*)&W[(size_t)(n0 + row0 + 32 * rep) * DMODEL + k0 + TBK + c4 * 4];
            }
        }

#pragma unroll
        for (int ks = 0; ks < 4; ks++) {
            const int kk = ks * 8;
            uint32_t af[4][4];
#pragma unroll
            for (int mt = 0; mt < 4; mt++) {
                const int mr = wm * 64 + mt * 16;
                af[mt][0] = __float_as_uint(As[mr + g    ][kk + t4    ]);
                af[mt][1] = __float_as_uint(As[mr + g + 8][kk + t4    ]);
                af[mt][2] = __float_as_uint(As[mr + g    ][kk + t4 + 4]);
                af[mt][3] = __float_as_uint(As[mr + g + 8][kk + t4 + 4]);
            }
            uint32_t bf[4][2];
#pragma unroll
            for (int nt = 0; nt < 4; nt++) {
                const int nc = wn * 32 + nt * 8;
                bf[nt][0] = __float_as_uint(Bs[nc + g][kk + t4    ]);
                bf[nt][1] = __float_as_uint(Bs[nc + g][kk + t4 + 4]);
            }
#pragma unroll
            for (int mt = 0; mt < 4; mt++)
#pragma unroll
                for (int nt = 0; nt < 4; nt++)
                    mma_tf32(acc[mt][nt], af[mt], bf[nt]);
        }
        __syncthreads();
    }

#pragma unroll
    for (int mt = 0; mt < 4; mt++) {
#pragma unroll
        for (int nt = 0; nt < 4; nt++) {
            const int n = n0 + wn * 32 + nt * 8 + t4 * 2;
            const float2 bv = *(const float2*)&bias[n];
#pragma unroll
            for (int half = 0; half < 2; half++) {
                const int m = m0 + wm * 64 + mt * 16 + g + half * 8;
                float2 v;
                v.x = acc[mt][nt][half * 2 + 0] + bv.x;
                v.y = acc[mt][nt][half * 2 + 1] + bv.y;
                if (split) {
                    const int b = m >> 11, s = m & 2047;
                    const int h = n >> 6,  dk = n & 63;
                    *(float2*)&C[(((size_t)(b * NHEAD + h)) * SEQ + s) * DK + dk] = v;
                } else {
                    *(float2*)&C[(size_t)m * DMODEL + n] = v;
                }
            }
        }
    }
}

struct QKVArgs {
    const float *x[3];      // query, key, value activations
    const float *W[3];      // Wq, Wk, Wv
    const float *b[3];      // bq, bk, bv
    float *out[3];          // g_Q, g_K, g_V
};

__global__ __launch_bounds__(256, 1) void qkv_gemm_kernel(QKVArgs args) {
    __shared__ float As[TBM][TBK + LDPAD];
    __shared__ float Bs[TBN][TBK + LDPAD];
    const int z = blockIdx.z;
    gemm_core(args.x[z], args.W[z], args.b[z], args.out[z], 1, As, Bs);
}

__global__ __launch_bounds__(256, 1) void o_gemm_kernel(
    const float* __restrict__ A, const float* __restrict__ W,
    const float* __restrict__ bias, float* __restrict__ C) {
    __shared__ float As[TBM][TBK + LDPAD];
    __shared__ float Bs[TBN][TBK + LDPAD];
    gemm_core(A, W, bias, C, 0, As, Bs);
}

// =============================================================================
// Tensor-core flash attention (causal), tf32 mma for QK^T and PV.
// Q,K,V: (B*H, S, DK) row-major.  Out: merged (B, S, D).
// Block: 128 q-rows of one (b,h), 8 warps; warp w owns m-tile rows w*16..+15.
// Key tile = 64. Softmax fully warp-local (quad shuffles).
// =============================================================================
#define FQ 128
#define KT 64
#define KS_ST 68   // bank(g*4+t4) conflict-free for K B-frags
#define VS_ST 72   // bank(t4*8+g) conflict-free for V B-frags
#define PS_ST 68   // conflict-free P A-frags / Q staging

__global__ __launch_bounds__(256, 1) void flash_mma_kernel(
    const float* __restrict__ Q, const float* __restrict__ K,
    const float* __restrict__ V, float* __restrict__ Out)
{
    extern __shared__ float sm[];
    float* Ks = sm;                       // [64][68]
    float* Vs = Ks + KT * KS_ST;          // [64][72]
    float* Ps = Vs + KT * VS_ST;          // [128][68] (Q staging, then P)

    const int qi = gridDim.x - 1 - blockIdx.x;   // longest blocks first
    const int bh = blockIdx.y;
    const int tid = threadIdx.x;
    const int w = tid >> 5, lane = tid & 31;
    const int g = lane >> 2, t4 = lane & 3;

    // ---- stage Q into Ps region, then cache scaled tf32 fragments in regs ----
    const float* Qg = Q + ((size_t)bh * SEQ + qi * FQ) * DK;
#pragma unroll
    for (int i = 0; i < 8; i++) {             // 128 rows x 16 float4
        int lin = tid + i * 256;
        int row = lin >> 4, c4 = lin & 15;
        float4 v = ((const float4*)(Qg + row * DK))[c4];
        *(float4*)&Ps[row * PS_ST + c4 * 4] = v;
    }
    __syncthreads();

    uint32_t qa[8][4];
    {
        const float* qr0 = &Ps[(w * 16 + g) * PS_ST];
        const float* qr1 = &Ps[(w * 16 + g + 8) * PS_ST];
#pragma unroll
        for (int kt = 0; kt < 8; kt++) {
            qa[kt][0] = __float_as_uint(to_tf32(qr0[kt * 8 + t4    ] * 0.125f));
            qa[kt][1] = __float_as_uint(to_tf32(qr1[kt * 8 + t4    ] * 0.125f));
            qa[kt][2] = __float_as_uint(to_tf32(qr0[kt * 8 + t4 + 4] * 0.125f));
            qa[kt][3] = __float_as_uint(to_tf32(qr1[kt * 8 + t4 + 4] * 0.125f));
        }
    }

    float m0 = -1e30f, m1 = -1e30f, l0 = 0.f, l1 = 0.f;
    float oacc[8][4];
#pragma unroll
    for (int nt = 0; nt < 8; nt++)
#pragma unroll
        for (int i = 0; i < 4; i++) oacc[nt][i] = 0.f;

    const int njb = 2 * qi + 2;
    const float* Kg = K + (size_t)bh * SEQ * DK;
    const float* Vg = V + (size_t)bh * SEQ * DK;

    // prefetch tile 0 into regs
    float4 kreg[4], vreg[4];
#pragma unroll
    for (int i = 0; i < 4; i++) {
        int lin = tid + i * 256;
        int row = lin >> 4, c4 = lin & 15;
        kreg[i] = ((const float4*)(Kg + row * DK))[c4];
        vreg[i] = ((const float4*)(Vg + row * DK))[c4];
    }

    const int row0 = qi * FQ + w * 16 + g;
    const int row1 = row0 + 8;

    for (int jb = 0; jb < njb; jb++) {
        __syncthreads();   // all warps done reading prev K/V tile
#pragma unroll
        for (int i = 0; i < 4; i++) {
            int lin = tid + i * 256;
            int row = lin >> 4, c4 = lin & 15;
            float* kd = &Ks[row * KS_ST + c4 * 4];
            kd[0] = to_tf32(kreg[i].x); kd[1] = to_tf32(kreg[i].y);
            kd[2] = to_tf32(kreg[i].z); kd[3] = to_tf32(kreg[i].w);
            float* vd = &Vs[row * VS_ST + c4 * 4];
            vd[0] = to_tf32(vreg[i].x); vd[1] = to_tf32(vreg[i].y);
            vd[2] = to_tf32(vreg[i].z); vd[3] = to_tf32(vreg[i].w);
        }
        __syncthreads();

        if (jb + 1 < njb) {   // prefetch next tile; overlaps compute below
            const float* Kn = Kg + (size_t)(jb + 1) * KT * DK;
            const float* Vn = Vg + (size_t)(jb + 1) * KT * DK;
#pragma unroll
            for (int i = 0; i < 4; i++) {
                int lin = tid + i * 256;
                int row = lin >> 4, c4 = lin & 15;
                kreg[i] = ((const float4*)(Kn + row * DK))[c4];
                vreg[i] = ((const float4*)(Vn + row * DK))[c4];
            }
        }

        // ---- S = Q K^T (warp 16x64 tile) ----
        float sacc[8][4];
#pragma unroll
        for (int nt = 0; nt < 8; nt++)
#pragma unroll
            for (int i = 0; i < 4; i++) sacc[nt][i] = 0.f;

#pragma unroll
        for (int kt = 0; kt < 8; kt++) {
#pragma unroll
            for (int nt = 0; nt < 8; nt++) {
                uint32_t kb[2];
                const float* kr = &Ks[(nt * 8 + g) * KS_ST + kt * 8];
                kb[0] = __float_as_uint(kr[t4]);
                kb[1] = __float_as_uint(kr[t4 + 4]);
                mma_tf32(sacc[nt], qa[kt], kb);
            }
        }

        // ---- causal mask (only last two tiles) ----
        if (jb >= 2 * qi) {
#pragma unroll
            for (int nt = 0; nt < 8; nt++) {
                int key = jb * KT + nt * 8 + 2 * t4;
                if (key     > row0) sacc[nt][0] = -1e30f;
                if (key + 1 > row0) sacc[nt][1] = -1e30f;
                if (key     > row1) sacc[nt][2] = -1e30f;
                if (key + 1 > row1) sacc[nt][3] = -1e30f;
            }
        }

        // ---- online softmax (warp-local; quad shuffles over t4) ----
        float mx0 = -1e30f, mx1 = -1e30f;
#pragma unroll
        for (int nt = 0; nt < 8; nt++) {
            mx0 = fmaxf(mx0, fmaxf(sacc[nt][0], sacc[nt][1]));
            mx1 = fmaxf(mx1, fmaxf(sacc[nt][2], sacc[nt][3]));
        }
        mx0 = fmaxf(mx0, __shfl_xor_sync(0xffffffffu, mx0, 1));
        mx0 = fmaxf(mx0, __shfl_xor_sync(0xffffffffu, mx0, 2));
        mx1 = fmaxf(mx1, __shfl_xor_sync(0xffffffffu, mx1, 1));
        mx1 = fmaxf(mx1, __shfl_xor_sync(0xffffffffu, mx1, 2));
        const float mn0 = fmaxf(m0, mx0);
        const float mn1 = fmaxf(m1, mx1);

        float sum0 = 0.f, sum1 = 0.f;
#pragma unroll
        for (int nt = 0; nt < 8; nt++) {
            float p00 = to_tf32(__expf(sacc[nt][0] - mn0));
            float p01 = to_tf32(__expf(sacc[nt][1] - mn0));
            float p10 = to_tf32(__expf(sacc[nt][2] - mn1));
            float p11 = to_tf32(__expf(sacc[nt][3] - mn1));
            sum0 += p00 + p01;
            sum1 += p10 + p11;
            sacc[nt][0] = p00; sacc[nt][1] = p01;
            sacc[nt][2] = p10; sacc[nt][3] = p11;
        }
        sum0 += __shfl_xor_sync(0xffffffffu, sum0, 1);
        sum0 += __shfl_xor_sync(0xffffffffu, sum0, 2);
        sum1 += __shfl_xor_sync(0xffffffffu, sum1, 1);
        sum1 += __shfl_xor_sync(0xffffffffu, sum1, 2);

        const float a0 = __expf(m0 - mn0);
        const float a1 = __expf(m1 - mn1);
        l0 = l0 * a0 + sum0;
        l1 = l1 * a1 + sum1;
        m0 = mn0; m1 = mn1;
#pragma unroll
        for (int nt = 0; nt < 8; nt++) {
            oacc[nt][0] *= a0; oacc[nt][1] *= a0;
            oacc[nt][2] *= a1; oacc[nt][3] *= a1;
        }

        // ---- P through smem (C-layout -> A-layout), warp-private region ----
        __syncwarp();
        float* prow0 = &Ps[(w * 16 + g) * PS_ST];
        float* prow1 = &Ps[(w * 16 + g + 8) * PS_ST];
#pragma unroll
        for (int nt = 0; nt < 8; nt++) {
            *(float2*)&prow0[nt * 8 + 2 * t4] = make_float2(sacc[nt][0], sacc[nt][1]);
            *(float2*)&prow1[nt * 8 + 2 * t4] = make_float2(sacc[nt][2], sacc[nt][3]);
        }
        __syncwarp();

        // ---- O += P V ----
#pragma unroll
        for (int kt = 0; kt < 8; kt++) {
            uint32_t pa[4];
            pa[0] = __float_as_uint(prow0[kt * 8 + t4    ]);
            pa[1] = __float_as_uint(prow1[kt * 8 + t4    ]);
            pa[2] = __float_as_uint(prow0[kt * 8 + t4 + 4]);
            pa[3] = __float_as_uint(prow1[kt * 8 + t4 + 4]);
#pragma unroll
            for (int nt = 0; nt < 8; nt++) {
                uint32_t vb[2];
                vb[0] = __float_as_uint(Vs[(kt * 8 + t4    ) * VS_ST + nt * 8 + g]);
                vb[1] = __float_as_uint(Vs[(kt * 8 + t4 + 4) * VS_ST + nt * 8 + g]);
                mma_tf32(oacc[nt], pa, vb);
            }
        }
    }

    // ---- normalize + write merged (B,S,D) ----
    const float i0 = 1.f / l0, i1 = 1.f / l1;
    const int b = bh >> 4, h = bh & 15;
#pragma unroll
    for (int nt = 0; nt < 8; nt++) {
        const int col = h * DK + nt * 8 + 2 * t4;
        float2 v0 = make_float2(oacc[nt][0] * i0, oacc[nt][1] * i0);
        float2 v1 = make_float2(oacc[nt][2] * i1, oacc[nt][3] * i1);
        *(float2*)&Out[((size_t)(b * SEQ + row0)) * DMODEL + col] = v0;
        *(float2*)&Out[((size_t)(b * SEQ + row1)) * DMODEL + col] = v1;
    }
}

// ---------------- launch ------------------------------------------------------
extern "C" void kernel_launch(void* const* d_in, const int* in_sizes, int n_in,
                              void* d_out, int out_size)
{
    const float* query = (const float*)d_in[0];
    const float* key   = (const float*)d_in[1];
    const float* value = (const float*)d_in[2];
    // d_in[3] = mask (causal triu, fixed by problem definition) -> analytic
    const float* Wq = (const float*)d_in[4];
    const float* bq = (const float*)d_in[5];
    const float* Wk = (const float*)d_in[6];
    const float* bk = (const float*)d_in[7];
    const float* Wv = (const float*)d_in[8];
    const float* bv = (const float*)d_in[9];
    const float* Wo = (const float*)d_in[10];
    const float* bo = (const float*)d_in[11];
    float* out = (float*)d_out;

    float *pQ, *pK, *pV, *pA;
    cudaGetSymbolAddress((void**)&pQ, g_Q);
    cudaGetSymbolAddress((void**)&pK, g_K);
    cudaGetSymbolAddress((void**)&pV, g_V);
    cudaGetSymbolAddress((void**)&pA, g_A);

    QKVArgs args;
    args.x[0] = query; args.x[1] = key; args.x[2] = value;
    args.W[0] = Wq;    args.W[1] = Wk;  args.W[2] = Wv;
    args.b[0] = bq;    args.b[1] = bk;  args.b[2] = bv;
    args.out[0] = pQ;  args.out[1] = pK; args.out[2] = pV;

    qkv_gemm_kernel<<<dim3(DMODEL / TBN, MROWS / TBM, 3), 256>>>(args);

    const int fl_smem = (KT * KS_ST + KT * VS_ST + FQ * PS_ST) * (int)sizeof(float); // 70656
    cudaFuncSetAttribute(flash_mma_kernel,
                         cudaFuncAttributeMaxDynamicSharedMemorySize, fl_smem);
    flash_mma_kernel<<<dim3(SEQ / FQ, BATCH * NHEAD), 256, fl_smem>>>(pQ, pK, pV, pA);

    o_gemm_kernel<<<dim3(DMODEL / TBN, MROWS / TBM), 256>>>(pA, Wo, bo, out);
}

// round 7
// speedup vs baseline: 3.1889x; 1.0460x over previous
#include <cuda_runtime.h>
#include <cuda_bf16.h>
#include <math.h>
#include <stdint.h>

// Problem constants
#define BATCH 2
#define SEQ   2048
#define DMODEL 1024
#define NHEAD 16
#define DK    64
#define MROWS (BATCH*SEQ)   // 4096

// ---------------- scratch (allocation-free rule: __device__ globals) ----------
__device__ float g_Q[MROWS * DMODEL];   // (B*H, S, DK), tf32-rounded, pre-scaled 1/8
__device__ float g_K[MROWS * DMODEL];   // tf32-rounded
__device__ float g_V[MROWS * DMODEL];   // tf32-rounded
__device__ float g_A[MROWS * DMODEL];   // attention output, merged (B,S,D), raw fp32

// =============================================================================
// helpers
// =============================================================================
__device__ __forceinline__ float to_tf32(float x) {
    float r;
    asm("cvt.rna.tf32.f32 %0, %1;" : "=f"(r) : "f"(x));
    return r;
}

__device__ __forceinline__ void mma_tf32(float* c, const uint32_t* a, const uint32_t* b) {
    asm volatile(
        "mma.sync.aligned.m16n8k8.row.col.f32.tf32.tf32.f32 "
        "{%0,%1,%2,%3}, {%4,%5,%6,%7}, {%8,%9}, {%0,%1,%2,%3};"
        : "+f"(c[0]), "+f"(c[1]), "+f"(c[2]), "+f"(c[3])
        : "r"(a[0]), "r"(a[1]), "r"(a[2]), "r"(a[3]), "r"(b[0]), "r"(b[1]));
}

__device__ __forceinline__ void cp16(uint32_t dst, const void* src) {
    asm volatile("cp.async.cg.shared.global [%0], [%1], 16;" :: "r"(dst), "l"(src));
}
__device__ __forceinline__ void cp_commit() { asm volatile("cp.async.commit_group;"); }
template<int N> __device__ __forceinline__ void cp_wait() {
    asm volatile("cp.async.wait_group %0;" :: "n"(N));
}

// =============================================================================
// tf32 GEMM: C[m,n] = sum_k A[m,k] * W[n,k] + bias[n]
// Block 128x128, K-tile 32, 2-stage cp.async pipeline, 8 warps (warp tile 64x32)
// A/W stored raw fp32 in smem; cvt.rna.tf32 applied at fragment load.
// split==1: scatter to ((b*H+h)*S+s)*DK+dk with tf32 rounding and premul.
// =============================================================================
#define TBM 128
#define TBN 128
#define TBK 32
#define AST 36                 // smem row stride (floats); 36*4=144B, 16B aligned
#define GEMM_STAGE (TBM*AST)   // floats per stage per matrix
#define NKT (DMODEL/TBK)       // 32

__device__ __forceinline__ void gemm_core(
    const float* __restrict__ A, const float* __restrict__ W,
    const float* __restrict__ bias, float* __restrict__ C,
    int split, float premul, float* As, float* Bs)
{
    const int tid  = threadIdx.x;
    const int wid  = tid >> 5;
    const int lane = tid & 31;
    const int wm   = wid & 1;
    const int wn   = wid >> 1;
    const int g    = lane >> 2;
    const int t4   = lane & 3;

    const int m0 = blockIdx.y * TBM;
    const int n0 = blockIdx.x * TBN;

    const int c4   = tid & 7;      // k-float4 index
    const int row0 = tid >> 3;     // rows row0 + 32*rep

    const uint32_t as_u = (uint32_t)__cvta_generic_to_shared(As);
    const uint32_t bs_u = (uint32_t)__cvta_generic_to_shared(Bs);

    float acc[4][4][4];
#pragma unroll
    for (int mt = 0; mt < 4; mt++)
#pragma unroll
        for (int nt = 0; nt < 4; nt++)
#pragma unroll
            for (int i = 0; i < 4; i++) acc[mt][nt][i] = 0.f;

    // issue stage 0
#pragma unroll
    for (int rep = 0; rep < 4; rep++) {
        const int row = row0 + 32 * rep;
        cp16(as_u + (uint32_t)(row * AST + c4 * 4) * 4,
             A + (size_t)(m0 + row) * DMODEL + c4 * 4);
        cp16(bs_u + (uint32_t)(row * AST + c4 * 4) * 4,
             W + (size_t)(n0 + row) * DMODEL + c4 * 4);
    }
    cp_commit();

    for (int t = 0; t < NKT; t++) {
        cp_wait<0>();
        __syncthreads();

        if (t + 1 < NKT) {
            const int st = (t + 1) & 1;
            const int k0 = (t + 1) * TBK;
#pragma unroll
            for (int rep = 0; rep < 4; rep++) {
                const int row = row0 + 32 * rep;
                cp16(as_u + (uint32_t)(st * GEMM_STAGE + row * AST + c4 * 4) * 4,
                     A + (size_t)(m0 + row) * DMODEL + k0 + c4 * 4);
                cp16(bs_u + (uint32_t)(st * GEMM_STAGE + row * AST + c4 * 4) * 4,
                     W + (size_t)(n0 + row) * DMODEL + k0 + c4 * 4);
            }
            cp_commit();
        }

        const float* a_s = As + (t & 1) * GEMM_STAGE;
        const float* b_s = Bs + (t & 1) * GEMM_STAGE;

#pragma unroll
        for (int ks = 0; ks < 4; ks++) {
            const int kk = ks * 8;
            uint32_t af[4][4];
#pragma unroll
            for (int mt = 0; mt < 4; mt++) {
                const int mr = wm * 64 + mt * 16;
                af[mt][0] = __float_as_uint(to_tf32(a_s[(mr + g    ) * AST + kk + t4    ]));
                af[mt][1] = __float_as_uint(to_tf32(a_s[(mr + g + 8) * AST + kk + t4    ]));
                af[mt][2] = __float_as_uint(to_tf32(a_s[(mr + g    ) * AST + kk + t4 + 4]));
                af[mt][3] = __float_as_uint(to_tf32(a_s[(mr + g + 8) * AST + kk + t4 + 4]));
            }
            uint32_t bf[4][2];
#pragma unroll
            for (int nt = 0; nt < 4; nt++) {
                const int nc = wn * 32 + nt * 8;
                bf[nt][0] = __float_as_uint(to_tf32(b_s[(nc + g) * AST + kk + t4    ]));
                bf[nt][1] = __float_as_uint(to_tf32(b_s[(nc + g) * AST + kk + t4 + 4]));
            }
#pragma unroll
            for (int mt = 0; mt < 4; mt++)
#pragma unroll
                for (int nt = 0; nt < 4; nt++)
                    mma_tf32(acc[mt][nt], af[mt], bf[nt]);
        }
    }

    // epilogue
#pragma unroll
    for (int mt = 0; mt < 4; mt++) {
#pragma unroll
        for (int nt = 0; nt < 4; nt++) {
            const int n = n0 + wn * 32 + nt * 8 + t4 * 2;
            const float2 bv = *(const float2*)&bias[n];
#pragma unroll
            for (int half = 0; half < 2; half++) {
                const int m = m0 + wm * 64 + mt * 16 + g + half * 8;
                float2 v;
                v.x = acc[mt][nt][half * 2 + 0] + bv.x;
                v.y = acc[mt][nt][half * 2 + 1] + bv.y;
                if (split) {
                    v.x = to_tf32(v.x * premul);
                    v.y = to_tf32(v.y * premul);
                    const int b = m >> 11, s = m & 2047;
                    const int h = n >> 6,  dk = n & 63;
                    *(float2*)&C[(((size_t)(b * NHEAD + h)) * SEQ + s) * DK + dk] = v;
                } else {
                    *(float2*)&C[(size_t)m * DMODEL + n] = v;
                }
            }
        }
    }
}

struct QKVArgs {
    const float *x[3];
    const float *W[3];
    const float *b[3];
    float *out[3];
};

#define GEMM_SMEM (2 * 2 * GEMM_STAGE * (int)sizeof(float))   // 73728

__global__ __launch_bounds__(256, 2) void qkv_gemm_kernel(QKVArgs args) {
    extern __shared__ float smg[];
    float* As = smg;
    float* Bs = smg + 2 * GEMM_STAGE;
    const int z = blockIdx.z;
    const float premul = (z == 0) ? 0.125f : 1.0f;   // fold 1/sqrt(dk) into Q
    gemm_core(args.x[z], args.W[z], args.b[z], args.out[z], 1, premul, As, Bs);
}

__global__ __launch_bounds__(256, 2) void o_gemm_kernel(
    const float* __restrict__ A, const float* __restrict__ W,
    const float* __restrict__ bias, float* __restrict__ C) {
    extern __shared__ float smg[];
    float* As = smg;
    float* Bs = smg + 2 * GEMM_STAGE;
    gemm_core(A, W, bias, C, 0, 1.0f, As, Bs);
}

// =============================================================================
// Tensor-core flash attention (causal), tf32 mma, 2-stage cp.async KV pipeline.
// Q,K,V: (B*H, S, DK), already tf32-rounded (Q pre-scaled). Out: merged (B,S,D).
// Block: 128 q-rows, 8 warps; warp w owns rows w*16..+15. Key tile 64.
// =============================================================================
#define FQ 128
#define KT 64
#define KS_ST 68   // bank(4g+t4) conflict-free
#define VS_ST 72   // bank(8t4+g) conflict-free
#define PS_ST 68
#define KS_STAGE (KT * KS_ST)
#define VS_STAGE (KT * VS_ST)
#define FLASH_SMEM ((2*KS_STAGE + 2*VS_STAGE + FQ*PS_ST) * (int)sizeof(float)) // 106496

__global__ __launch_bounds__(256, 2) void flash_mma_kernel(
    const float* __restrict__ Q, const float* __restrict__ K,
    const float* __restrict__ V, float* __restrict__ Out)
{
    extern __shared__ float sm[];
    float* Ks = sm;                         // [2][64][68]
    float* Vs = Ks + 2 * KS_STAGE;          // [2][64][72]
    float* Ps = Vs + 2 * VS_STAGE;          // [128][68] (Q staging, then P)

    const int qi = gridDim.x - 1 - blockIdx.x;   // longest blocks first
    const int bh = blockIdx.y;
    const int tid = threadIdx.x;
    const int w = tid >> 5, lane = tid & 31;
    const int g = lane >> 2, t4 = lane & 3;

    const uint32_t ks_u = (uint32_t)__cvta_generic_to_shared(Ks);
    const uint32_t vs_u = (uint32_t)__cvta_generic_to_shared(Vs);
    const uint32_t ps_u = (uint32_t)__cvta_generic_to_shared(Ps);

    const float* Qg = Q + ((size_t)bh * SEQ + qi * FQ) * DK;
    const float* Kg = K + (size_t)bh * SEQ * DK;
    const float* Vg = V + (size_t)bh * SEQ * DK;

    // group 0: Q -> Ps
#pragma unroll
    for (int i = 0; i < 8; i++) {
        int lin = tid + i * 256;
        int row = lin >> 4, c4 = lin & 15;
        cp16(ps_u + (uint32_t)(row * PS_ST + c4 * 4) * 4, Qg + row * DK + c4 * 4);
    }
    cp_commit();

    // group 1: KV tile 0
#pragma unroll
    for (int i = 0; i < 4; i++) {
        int lin = tid + i * 256;
        int row = lin >> 4, c4 = lin & 15;
        cp16(ks_u + (uint32_t)(row * KS_ST + c4 * 4) * 4, Kg + row * DK + c4 * 4);
        cp16(vs_u + (uint32_t)(row * VS_ST + c4 * 4) * 4, Vg + row * DK + c4 * 4);
    }
    cp_commit();

    cp_wait<1>();          // Q resident (KV0 may still be in flight)
    __syncthreads();

    // cache Q fragments (already tf32 + scaled)
    uint32_t qa[8][4];
    {
        const float* qr0 = &Ps[(w * 16 + g) * PS_ST];
        const float* qr1 = &Ps[(w * 16 + g + 8) * PS_ST];
#pragma unroll
        for (int kt = 0; kt < 8; kt++) {
            qa[kt][0] = __float_as_uint(qr0[kt * 8 + t4    ]);
            qa[kt][1] = __float_as_uint(qr1[kt * 8 + t4    ]);
            qa[kt][2] = __float_as_uint(qr0[kt * 8 + t4 + 4]);
            qa[kt][3] = __float_as_uint(qr1[kt * 8 + t4 + 4]);
        }
    }

    float m0 = -1e30f, m1 = -1e30f, l0 = 0.f, l1 = 0.f;
    float oacc[8][4];
#pragma unroll
    for (int nt = 0; nt < 8; nt++)
#pragma unroll
        for (int i = 0; i < 4; i++) oacc[nt][i] = 0.f;

    const int njb = 2 * qi + 2;
    const int row0 = qi * FQ + w * 16 + g;
    const int row1 = row0 + 8;

    for (int jb = 0; jb < njb; jb++) {
        cp_wait<0>();
        __syncthreads();

        if (jb + 1 < njb) {   // prefetch next KV tile into other stage
            const int st = (jb + 1) & 1;
            const float* Kn = Kg + (size_t)(jb + 1) * KT * DK;
            const float* Vn = Vg + (size_t)(jb + 1) * KT * DK;
#pragma unroll
            for (int i = 0; i < 4; i++) {
                int lin = tid + i * 256;
                int row = lin >> 4, c4 = lin & 15;
                cp16(ks_u + (uint32_t)(st * KS_STAGE + row * KS_ST + c4 * 4) * 4,
                     Kn + row * DK + c4 * 4);
                cp16(vs_u + (uint32_t)(st * VS_STAGE + row * VS_ST + c4 * 4) * 4,
                     Vn + row * DK + c4 * 4);
            }
            cp_commit();
        }

        const float* k_s = Ks + (jb & 1) * KS_STAGE;
        const float* v_s = Vs + (jb & 1) * VS_STAGE;

        // ---- S = Q K^T (warp 16x64 tile) ----
        float sacc[8][4];
#pragma unroll
        for (int nt = 0; nt < 8; nt++)
#pragma unroll
            for (int i = 0; i < 4; i++) sacc[nt][i] = 0.f;

#pragma unroll
        for (int kt = 0; kt < 8; kt++) {
#pragma unroll
            for (int nt = 0; nt < 8; nt++) {
                uint32_t kb[2];
                const float* kr = &k_s[(nt * 8 + g) * KS_ST + kt * 8];
                kb[0] = __float_as_uint(kr[t4]);
                kb[1] = __float_as_uint(kr[t4 + 4]);
                mma_tf32(sacc[nt], qa[kt], kb);
            }
        }

        // ---- causal mask (only last two tiles) ----
        if (jb >= 2 * qi) {
#pragma unroll
            for (int nt = 0; nt < 8; nt++) {
                int key = jb * KT + nt * 8 + 2 * t4;
                if (key     > row0) sacc[nt][0] = -1e30f;
                if (key + 1 > row0) sacc[nt][1] = -1e30f;
                if (key     > row1) sacc[nt][2] = -1e30f;
                if (key + 1 > row1) sacc[nt][3] = -1e30f;
            }
        }

        // ---- online softmax (warp-local) ----
        float mx0 = -1e30f, mx1 = -1e30f;
#pragma unroll
        for (int nt = 0; nt < 8; nt++) {
            mx0 = fmaxf(mx0, fmaxf(sacc[nt][0], sacc[nt][1]));
            mx1 = fmaxf(mx1, fmaxf(sacc[nt][2], sacc[nt][3]));
        }
        mx0 = fmaxf(mx0, __shfl_xor_sync(0xffffffffu, mx0, 1));
        mx0 = fmaxf(mx0, __shfl_xor_sync(0xffffffffu, mx0, 2));
        mx1 = fmaxf(mx1, __shfl_xor_sync(0xffffffffu, mx1, 1));
        mx1 = fmaxf(mx1, __shfl_xor_sync(0xffffffffu, mx1, 2));
        const float mn0 = fmaxf(m0, mx0);
        const float mn1 = fmaxf(m1, mx1);

        float sum0 = 0.f, sum1 = 0.f;
#pragma unroll
        for (int nt = 0; nt < 8; nt++) {
            float p00 = to_tf32(__expf(sacc[nt][0] - mn0));
            float p01 = to_tf32(__expf(sacc[nt][1] - mn0));
            float p10 = to_tf32(__expf(sacc[nt][2] - mn1));
            float p11 = to_tf32(__expf(sacc[nt][3] - mn1));
            sum0 += p00 + p01;
            sum1 += p10 + p11;
            sacc[nt][0] = p00; sacc[nt][1] = p01;
            sacc[nt][2] = p10; sacc[nt][3] = p11;
        }
        sum0 += __shfl_xor_sync(0xffffffffu, sum0, 1);
        sum0 += __shfl_xor_sync(0xffffffffu, sum0, 2);
        sum1 += __shfl_xor_sync(0xffffffffu, sum1, 1);
        sum1 += __shfl_xor_sync(0xffffffffu, sum1, 2);

        const float a0 = __expf(m0 - mn0);
        const float a1 = __expf(m1 - mn1);
        l0 = l0 * a0 + sum0;
        l1 = l1 * a1 + sum1;
        m0 = mn0; m1 = mn1;
#pragma unroll
        for (int nt = 0; nt < 8; nt++) {
            oacc[nt][0] *= a0; oacc[nt][1] *= a0;
            oacc[nt][2] *= a1; oacc[nt][3] *= a1;
        }

        // ---- P through smem (C-layout -> A-layout), warp-private rows ----
        __syncwarp();
        float* prow0 = &Ps[(w * 16 + g) * PS_ST];
        float* prow1 = &Ps[(w * 16 + g + 8) * PS_ST];
#pragma unroll
        for (int nt = 0; nt < 8; nt++) {
            *(float2*)&prow0[nt * 8 + 2 * t4] = make_float2(sacc[nt][0], sacc[nt][1]);
            *(float2*)&prow1[nt * 8 + 2 * t4] = make_float2(sacc[nt][2], sacc[nt][3]);
        }
        __syncwarp();

        // ---- O += P V ----
#pragma unroll
        for (int kt = 0; kt < 8; kt++) {
            uint32_t pa[4];
            pa[0] = __float_as_uint(prow0[kt * 8 + t4    ]);
            pa[1] = __float_as_uint(prow1[kt * 8 + t4    ]);
            pa[2] = __float_as_uint(prow0[kt * 8 + t4 + 4]);
            pa[3] = __float_as_uint(prow1[kt * 8 + t4 + 4]);
#pragma unroll
            for (int nt = 0; nt < 8; nt++) {
                uint32_t vb[2];
                vb[0] = __float_as_uint(v_s[(kt * 8 + t4    ) * VS_ST + nt * 8 + g]);
                vb[1] = __float_as_uint(v_s[(kt * 8 + t4 + 4) * VS_ST + nt * 8 + g]);
                mma_tf32(oacc[nt], pa, vb);
            }
        }
    }

    // ---- normalize + write merged (B,S,D) ----
    const float i0 = 1.f / l0, i1 = 1.f / l1;
    const int b = bh >> 4, h = bh & 15;
#pragma unroll
    for (int nt = 0; nt < 8; nt++) {
        const int col = h * DK + nt * 8 + 2 * t4;
        float2 v0 = make_float2(oacc[nt][0] * i0, oacc[nt][1] * i0);
        float2 v1 = make_float2(oacc[nt][2] * i1, oacc[nt][3] * i1);
        *(float2*)&Out[((size_t)(b * SEQ + row0)) * DMODEL + col] = v0;
        *(float2*)&Out[((size_t)(b * SEQ + row1)) * DMODEL + col] = v1;
    }
}

// ---------------- launch ------------------------------------------------------
extern "C" void kernel_launch(void* const* d_in, const int* in_sizes, int n_in,
                              void* d_out, int out_size)
{
    const float* query = (const float*)d_in[0];
    const float* key   = (const float*)d_in[1];
    const float* value = (const float*)d_in[2];
    // d_in[3] = mask (causal triu, fixed by problem definition) -> analytic
    const float* Wq = (const float*)d_in[4];
    const float* bq = (const float*)d_in[5];
    const float* Wk = (const float*)d_in[6];
    const float* bk = (const float*)d_in[7];
    const float* Wv = (const float*)d_in[8];
    const float* bv = (const float*)d_in[9];
    const float* Wo = (const float*)d_in[10];
    const float* bo = (const float*)d_in[11];
    float* out = (float*)d_out;

    float *pQ, *pK, *pV, *pA;
    cudaGetSymbolAddress((void**)&pQ, g_Q);
    cudaGetSymbolAddress((void**)&pK, g_K);
    cudaGetSymbolAddress((void**)&pV, g_V);
    cudaGetSymbolAddress((void**)&pA, g_A);

    cudaFuncSetAttribute(qkv_gemm_kernel,
                         cudaFuncAttributeMaxDynamicSharedMemorySize, GEMM_SMEM);
    cudaFuncSetAttribute(o_gemm_kernel,
                         cudaFuncAttributeMaxDynamicSharedMemorySize, GEMM_SMEM);
    cudaFuncSetAttribute(flash_mma_kernel,
                         cudaFuncAttributeMaxDynamicSharedMemorySize, FLASH_SMEM);

    QKVArgs args;
    args.x[0] = query; args.x[1] = key; args.x[2] = value;
    args.W[0] = Wq;    args.W[1] = Wk;  args.W[2] = Wv;
    args.b[0] = bq;    args.b[1] = bk;  args.b[2] = bv;
    args.out[0] = pQ;  args.out[1] = pK; args.out[2] = pV;

    qkv_gemm_kernel<<<dim3(DMODEL / TBN, MROWS / TBM, 3), 256, GEMM_SMEM>>>(args);

    flash_mma_kernel<<<dim3(SEQ / FQ, BATCH * NHEAD), 256, FLASH_SMEM>>>(pQ, pK, pV, pA);

    o_gemm_kernel<<<dim3(DMODEL / TBN, MROWS / TBM), 256, GEMM_SMEM>>>(pA, Wo, bo, out);
}

// round 8
// speedup vs baseline: 3.2158x; 1.0084x over previous
#include <cuda_runtime.h>
#include <cuda_bf16.h>
#include <math.h>
#include <stdint.h>

// Problem constants
#define BATCH 2
#define SEQ   2048
#define DMODEL 1024
#define NHEAD 16
#define DK    64
#define MROWS (BATCH*SEQ)   // 4096

// ---------------- scratch (allocation-free rule: __device__ globals) ----------
__device__ float g_Q[MROWS * DMODEL];   // (B*H, S, DK), tf32-rounded, pre-scaled 1/8
__device__ float g_K[MROWS * DMODEL];   // tf32-rounded
__device__ float g_V[MROWS * DMODEL];   // tf32-rounded
__device__ float g_A[MROWS * DMODEL];   // attention out, merged (B,S,D), tf32-rounded
// pre-rounded (tf32) copies of raw inputs
__device__ float g_rq[MROWS * DMODEL];
__device__ float g_rk[MROWS * DMODEL];
__device__ float g_rv[MROWS * DMODEL];
__device__ float g_rwq[DMODEL * DMODEL];
__device__ float g_rwk[DMODEL * DMODEL];
__device__ float g_rwv[DMODEL * DMODEL];
__device__ float g_rwo[DMODEL * DMODEL];

// =============================================================================
// helpers
// =============================================================================
__device__ __forceinline__ float to_tf32(float x) {
    float r;
    asm("cvt.rna.tf32.f32 %0, %1;" : "=f"(r) : "f"(x));
    return r;
}

__device__ __forceinline__ void mma_tf32(float* c, const uint32_t* a, const uint32_t* b) {
    asm volatile(
        "mma.sync.aligned.m16n8k8.row.col.f32.tf32.tf32.f32 "
        "{%0,%1,%2,%3}, {%4,%5,%6,%7}, {%8,%9}, {%0,%1,%2,%3};"
        : "+f"(c[0]), "+f"(c[1]), "+f"(c[2]), "+f"(c[3])
        : "r"(a[0]), "r"(a[1]), "r"(a[2]), "r"(a[3]), "r"(b[0]), "r"(b[1]));
}

// x4 ldmatrix on fp32 data (b16-pair view). Per 8x4-tf32 submatrix, lane L gets
// element [row L/4][col L%4] -> exactly the tf32 m16n8k8 fragment layouts.
__device__ __forceinline__ void ldsm4(uint32_t* r, uint32_t saddr) {
    asm volatile("ldmatrix.sync.aligned.m8n8.x4.shared.b16 {%0,%1,%2,%3}, [%4];"
                 : "=r"(r[0]), "=r"(r[1]), "=r"(r[2]), "=r"(r[3]) : "r"(saddr));
}

__device__ __forceinline__ void cp16(uint32_t dst, const void* src) {
    asm volatile("cp.async.cg.shared.global [%0], [%1], 16;" :: "r"(dst), "l"(src));
}
__device__ __forceinline__ void cp_commit() { asm volatile("cp.async.commit_group;"); }
template<int N> __device__ __forceinline__ void cp_wait() {
    asm volatile("cp.async.wait_group %0;" :: "n"(N));
}

// ---------------- pre-round pass: dst[i] = tf32_rna(src[i]) -------------------
__global__ __launch_bounds__(256) void round_tf32_kernel(
    const float4* __restrict__ src, float4* __restrict__ dst, int n4)
{
    int i = blockIdx.x * blockDim.x + threadIdx.x;
    if (i < n4) {
        float4 v = src[i];
        v.x = to_tf32(v.x); v.y = to_tf32(v.y);
        v.z = to_tf32(v.z); v.w = to_tf32(v.w);
        dst[i] = v;
    }
}

// =============================================================================
// tf32 GEMM: C[m,n] = sum_k A[m,k]*W[n,k] + bias[n]; inputs pre-rounded tf32.
// Block 128x128, K-tile 32, 2-stage cp.async, 8 warps (warp tile 64x32), LDSM.
// =============================================================================
#define TBM 128
#define TBN 128
#define TBK 32
#define AST 36                 // 144B row stride: LDSM bank-phase 4r mod 32 -> conflict-free
#define GEMM_STAGE (TBM*AST)
#define NKT (DMODEL/TBK)       // 32

__device__ __forceinline__ void gemm_core(
    const float* __restrict__ A, const float* __restrict__ W,
    const float* __restrict__ bias, float* __restrict__ C,
    int split, float premul, float* As, float* Bs)
{
    const int tid  = threadIdx.x;
    const int wid  = tid >> 5;
    const int lane = tid & 31;
    const int wm   = wid & 1;
    const int wn   = wid >> 1;
    const int g    = lane >> 2;
    const int t4   = lane & 3;
    const int l15  = lane & 15;          // ldmatrix row within 16
    const int lc4  = (lane >> 4) * 4;    // ldmatrix col half (0 or 4)

    const int m0 = blockIdx.y * TBM;
    const int n0 = blockIdx.x * TBN;

    const int c4   = tid & 7;
    const int row0 = tid >> 3;

    const uint32_t as_u = (uint32_t)__cvta_generic_to_shared(As);
    const uint32_t bs_u = (uint32_t)__cvta_generic_to_shared(Bs);

    float acc[4][4][4];
#pragma unroll
    for (int mt = 0; mt < 4; mt++)
#pragma unroll
        for (int nt = 0; nt < 4; nt++)
#pragma unroll
            for (int i = 0; i < 4; i++) acc[mt][nt][i] = 0.f;

    // stage 0
#pragma unroll
    for (int rep = 0; rep < 4; rep++) {
        const int row = row0 + 32 * rep;
        cp16(as_u + (uint32_t)(row * AST + c4 * 4) * 4,
             A + (size_t)(m0 + row) * DMODEL + c4 * 4);
        cp16(bs_u + (uint32_t)(row * AST + c4 * 4) * 4,
             W + (size_t)(n0 + row) * DMODEL + c4 * 4);
    }
    cp_commit();

    for (int t = 0; t < NKT; t++) {
        cp_wait<0>();
        __syncthreads();

        if (t + 1 < NKT) {
            const int st = (t + 1) & 1;
            const int k0 = (t + 1) * TBK;
#pragma unroll
            for (int rep = 0; rep < 4; rep++) {
                const int row = row0 + 32 * rep;
                cp16(as_u + (uint32_t)(st * GEMM_STAGE + row * AST + c4 * 4) * 4,
                     A + (size_t)(m0 + row) * DMODEL + k0 + c4 * 4);
                cp16(bs_u + (uint32_t)(st * GEMM_STAGE + row * AST + c4 * 4) * 4,
                     W + (size_t)(n0 + row) * DMODEL + k0 + c4 * 4);
            }
            cp_commit();
        }

        const uint32_t a_su = as_u + (uint32_t)((t & 1) * GEMM_STAGE) * 4;
        const uint32_t b_su = bs_u + (uint32_t)((t & 1) * GEMM_STAGE) * 4;

#pragma unroll
        for (int ks = 0; ks < 4; ks++) {
            const int kk = ks * 8;
            uint32_t af[4][4];
#pragma unroll
            for (int mt = 0; mt < 4; mt++)
                ldsm4(af[mt], a_su + (uint32_t)((wm * 64 + mt * 16 + l15) * AST + kk + lc4) * 4);
            uint32_t bfr[2][4];
#pragma unroll
            for (int np = 0; np < 2; np++)
                ldsm4(bfr[np], b_su + (uint32_t)((wn * 32 + np * 16 + l15) * AST + kk + lc4) * 4);
#pragma unroll
            for (int mt = 0; mt < 4; mt++)
#pragma unroll
                for (int nt = 0; nt < 4; nt++) {
                    uint32_t b[2];
                    b[0] = (nt & 1) ? bfr[nt >> 1][1] : bfr[nt >> 1][0];
                    b[1] = (nt & 1) ? bfr[nt >> 1][3] : bfr[nt >> 1][2];
                    mma_tf32(acc[mt][nt], af[mt], b);
                }
        }
    }

    // epilogue
#pragma unroll
    for (int mt = 0; mt < 4; mt++) {
#pragma unroll
        for (int nt = 0; nt < 4; nt++) {
            const int n = n0 + wn * 32 + nt * 8 + t4 * 2;
            const float2 bv = *(const float2*)&bias[n];
#pragma unroll
            for (int half = 0; half < 2; half++) {
                const int m = m0 + wm * 64 + mt * 16 + g + half * 8;
                float2 v;
                v.x = acc[mt][nt][half * 2 + 0] + bv.x;
                v.y = acc[mt][nt][half * 2 + 1] + bv.y;
                if (split) {
                    v.x = to_tf32(v.x * premul);
                    v.y = to_tf32(v.y * premul);
                    const int b = m >> 11, s = m & 2047;
                    const int h = n >> 6,  dk = n & 63;
                    *(float2*)&C[(((size_t)(b * NHEAD + h)) * SEQ + s) * DK + dk] = v;
                } else {
                    *(float2*)&C[(size_t)m * DMODEL + n] = v;
                }
            }
        }
    }
}

struct QKVArgs {
    const float *x[3];
    const float *W[3];
    const float *b[3];
    float *out[3];
};

#define GEMM_SMEM (2 * 2 * GEMM_STAGE * (int)sizeof(float))   // 73728

__global__ __launch_bounds__(256, 2) void qkv_gemm_kernel(QKVArgs args) {
    extern __shared__ float smg[];
    float* As = smg;
    float* Bs = smg + 2 * GEMM_STAGE;
    const int z = blockIdx.z;
    const float premul = (z == 0) ? 0.125f : 1.0f;   // fold 1/sqrt(dk) into Q
    gemm_core(args.x[z], args.W[z], args.b[z], args.out[z], 1, premul, As, Bs);
}

__global__ __launch_bounds__(256, 2) void o_gemm_kernel(
    const float* __restrict__ A, const float* __restrict__ W,
    const float* __restrict__ bias, float* __restrict__ C) {
    extern __shared__ float smg[];
    float* As = smg;
    float* Bs = smg + 2 * GEMM_STAGE;
    gemm_core(A, W, bias, C, 0, 1.0f, As, Bs);
}

// =============================================================================
// Tensor-core flash attention (causal), tf32 mma, cp.async KV pipeline, LDSM.
// Q,K,V: (B*H, S, DK), tf32-rounded (Q pre-scaled). Out: merged (B,S,D), tf32.
// Block: 128 q-rows, 8 warps; warp w owns rows w*16..+15. Key tile 64.
// =============================================================================
#define FQ 128
#define KT 64
#define KS_ST 68   // 272B stride: LDSM bank-phase 4r mod 32 -> conflict-free
#define VS_ST 72   // bank(8t4+g) conflict-free scalar pattern
#define PS_ST 68
#define KS_STAGE (KT * KS_ST)
#define VS_STAGE (KT * VS_ST)
#define FLASH_SMEM ((2*KS_STAGE + 2*VS_STAGE + FQ*PS_ST) * (int)sizeof(float)) // 106496

__global__ __launch_bounds__(256, 2) void flash_mma_kernel(
    const float* __restrict__ Q, const float* __restrict__ K,
    const float* __restrict__ V, float* __restrict__ Out)
{
    extern __shared__ float sm[];
    float* Ks = sm;                         // [2][64][68]
    float* Vs = Ks + 2 * KS_STAGE;          // [2][64][72]
    float* Ps = Vs + 2 * VS_STAGE;          // [128][68] (Q staging, then P)

    const int qi = gridDim.x - 1 - blockIdx.x;   // longest blocks first
    const int bh = blockIdx.y;
    const int tid = threadIdx.x;
    const int w = tid >> 5, lane = tid & 31;
    const int g = lane >> 2, t4 = lane & 3;
    const int l15 = lane & 15;
    const int lc4 = (lane >> 4) * 4;

    const uint32_t ks_u = (uint32_t)__cvta_generic_to_shared(Ks);
    const uint32_t vs_u = (uint32_t)__cvta_generic_to_shared(Vs);
    const uint32_t ps_u = (uint32_t)__cvta_generic_to_shared(Ps);

    const float* Qg = Q + ((size_t)bh * SEQ + qi * FQ) * DK;
    const float* Kg = K + (size_t)bh * SEQ * DK;
    const float* Vg = V + (size_t)bh * SEQ * DK;

    // group 0: Q -> Ps
#pragma unroll
    for (int i = 0; i < 8; i++) {
        int lin = tid + i * 256;
        int row = lin >> 4, c4 = lin & 15;
        cp16(ps_u + (uint32_t)(row * PS_ST + c4 * 4) * 4, Qg + row * DK + c4 * 4);
    }
    cp_commit();

    // group 1: KV tile 0
#pragma unroll
    for (int i = 0; i < 4; i++) {
        int lin = tid + i * 256;
        int row = lin >> 4, c4 = lin & 15;
        cp16(ks_u + (uint32_t)(row * KS_ST + c4 * 4) * 4, Kg + row * DK + c4 * 4);
        cp16(vs_u + (uint32_t)(row * VS_ST + c4 * 4) * 4, Vg + row * DK + c4 * 4);
    }
    cp_commit();

    cp_wait<1>();          // Q resident (KV0 may still be in flight)
    __syncthreads();

    // cache Q fragments via LDSM (already tf32 + scaled)
    uint32_t qa[8][4];
#pragma unroll
    for (int kt = 0; kt < 8; kt++)
        ldsm4(qa[kt], ps_u + (uint32_t)((w * 16 + l15) * PS_ST + kt * 8 + lc4) * 4);

    float m0 = -1e30f, m1 = -1e30f, l0 = 0.f, l1 = 0.f;
    float oacc[8][4];
#pragma unroll
    for (int nt = 0; nt < 8; nt++)
#pragma unroll
        for (int i = 0; i < 4; i++) oacc[nt][i] = 0.f;

    const int njb = 2 * qi + 2;
    const int row0 = qi * FQ + w * 16 + g;
    const int row1 = row0 + 8;

    for (int jb = 0; jb < njb; jb++) {
        cp_wait<0>();
        __syncthreads();

        if (jb + 1 < njb) {
            const int st = (jb + 1) & 1;
            const float* Kn = Kg + (size_t)(jb + 1) * KT * DK;
            const float* Vn = Vg + (size_t)(jb + 1) * KT * DK;
#pragma unroll
            for (int i = 0; i < 4; i++) {
                int lin = tid + i * 256;
                int row = lin >> 4, c4 = lin & 15;
                cp16(ks_u + (uint32_t)(st * KS_STAGE + row * KS_ST + c4 * 4) * 4,
                     Kn + row * DK + c4 * 4);
                cp16(vs_u + (uint32_t)(st * VS_STAGE + row * VS_ST + c4 * 4) * 4,
                     Vn + row * DK + c4 * 4);
            }
            cp_commit();
        }

        const uint32_t k_su = ks_u + (uint32_t)((jb & 1) * KS_STAGE) * 4;
        const float* v_s = Vs + (jb & 1) * VS_STAGE;

        // ---- S = Q K^T (warp 16x64 tile), K frags via LDSM ----
        float sacc[8][4];
#pragma unroll
        for (int nt = 0; nt < 8; nt++)
#pragma unroll
            for (int i = 0; i < 4; i++) sacc[nt][i] = 0.f;

#pragma unroll
        for (int kt = 0; kt < 8; kt++) {
            uint32_t kfr[4][4];
#pragma unroll
            for (int np = 0; np < 4; np++)
                ldsm4(kfr[np], k_su + (uint32_t)((np * 16 + l15) * KS_ST + kt * 8 + lc4) * 4);
#pragma unroll
            for (int nt = 0; nt < 8; nt++) {
                uint32_t b[2];
                b[0] = (nt & 1) ? kfr[nt >> 1][1] : kfr[nt >> 1][0];
                b[1] = (nt & 1) ? kfr[nt >> 1][3] : kfr[nt >> 1][2];
                mma_tf32(sacc[nt], qa[kt], b);
            }
        }

        // ---- causal mask (only last two tiles) ----
        if (jb >= 2 * qi) {
#pragma unroll
            for (int nt = 0; nt < 8; nt++) {
                int key = jb * KT + nt * 8 + 2 * t4;
                if (key     > row0) sacc[nt][0] = -1e30f;
                if (key + 1 > row0) sacc[nt][1] = -1e30f;
                if (key     > row1) sacc[nt][2] = -1e30f;
                if (key + 1 > row1) sacc[nt][3] = -1e30f;
            }
        }

        // ---- online softmax (warp-local) ----
        float mx0 = -1e30f, mx1 = -1e30f;
#pragma unroll
        for (int nt = 0; nt < 8; nt++) {
            mx0 = fmaxf(mx0, fmaxf(sacc[nt][0], sacc[nt][1]));
            mx1 = fmaxf(mx1, fmaxf(sacc[nt][2], sacc[nt][3]));
        }
        mx0 = fmaxf(mx0, __shfl_xor_sync(0xffffffffu, mx0, 1));
        mx0 = fmaxf(mx0, __shfl_xor_sync(0xffffffffu, mx0, 2));
        mx1 = fmaxf(mx1, __shfl_xor_sync(0xffffffffu, mx1, 1));
        mx1 = fmaxf(mx1, __shfl_xor_sync(0xffffffffu, mx1, 2));
        const float mn0 = fmaxf(m0, mx0);
        const float mn1 = fmaxf(m1, mx1);

        float sum0 = 0.f, sum1 = 0.f;
#pragma unroll
        for (int nt = 0; nt < 8; nt++) {
            float p00 = to_tf32(__expf(sacc[nt][0] - mn0));
            float p01 = to_tf32(__expf(sacc[nt][1] - mn0));
            float p10 = to_tf32(__expf(sacc[nt][2] - mn1));
            float p11 = to_tf32(__expf(sacc[nt][3] - mn1));
            sum0 += p00 + p01;
            sum1 += p10 + p11;
            sacc[nt][0] = p00; sacc[nt][1] = p01;
            sacc[nt][2] = p10; sacc[nt][3] = p11;
        }
        sum0 += __shfl_xor_sync(0xffffffffu, sum0, 1);
        sum0 += __shfl_xor_sync(0xffffffffu, sum0, 2);
        sum1 += __shfl_xor_sync(0xffffffffu, sum1, 1);
        sum1 += __shfl_xor_sync(0xffffffffu, sum1, 2);

        const float a0 = __expf(m0 - mn0);
        const float a1 = __expf(m1 - mn1);
        l0 = l0 * a0 + sum0;
        l1 = l1 * a1 + sum1;
        m0 = mn0; m1 = mn1;
#pragma unroll
        for (int nt = 0; nt < 8; nt++) {
            oacc[nt][0] *= a0; oacc[nt][1] *= a0;
            oacc[nt][2] *= a1; oacc[nt][3] *= a1;
        }

        // ---- P through smem (C-layout -> A-layout), warp-private rows ----
        __syncwarp();
        float* prow0 = &Ps[(w * 16 + g) * PS_ST];
        float* prow1 = &Ps[(w * 16 + g + 8) * PS_ST];
#pragma unroll
        for (int nt = 0; nt < 8; nt++) {
            *(float2*)&prow0[nt * 8 + 2 * t4] = make_float2(sacc[nt][0], sacc[nt][1]);
            *(float2*)&prow1[nt * 8 + 2 * t4] = make_float2(sacc[nt][2], sacc[nt][3]);
        }
        __syncwarp();

        // ---- O += P V ; P A-frags via LDSM, V scalar ----
#pragma unroll
        for (int kt = 0; kt < 8; kt++) {
            uint32_t pa[4];
            ldsm4(pa, ps_u + (uint32_t)((w * 16 + l15) * PS_ST + kt * 8 + lc4) * 4);
#pragma unroll
            for (int nt = 0; nt < 8; nt++) {
                uint32_t vb[2];
                vb[0] = __float_as_uint(v_s[(kt * 8 + t4    ) * VS_ST + nt * 8 + g]);
                vb[1] = __float_as_uint(v_s[(kt * 8 + t4 + 4) * VS_ST + nt * 8 + g]);
                mma_tf32(oacc[nt], pa, vb);
            }
        }
    }

    // ---- normalize + write merged (B,S,D), tf32-rounded for O GEMM ----
    const float i0 = 1.f / l0, i1 = 1.f / l1;
    const int b = bh >> 4, h = bh & 15;
#pragma unroll
    for (int nt = 0; nt < 8; nt++) {
        const int col = h * DK + nt * 8 + 2 * t4;
        float2 v0 = make_float2(to_tf32(oacc[nt][0] * i0), to_tf32(oacc[nt][1] * i0));
        float2 v1 = make_float2(to_tf32(oacc[nt][2] * i1), to_tf32(oacc[nt][3] * i1));
        *(float2*)&Out[((size_t)(b * SEQ + row0)) * DMODEL + col] = v0;
        *(float2*)&Out[((size_t)(b * SEQ + row1)) * DMODEL + col] = v1;
    }
}

// ---------------- launch ------------------------------------------------------
extern "C" void kernel_launch(void* const* d_in, const int* in_sizes, int n_in,
                              void* d_out, int out_size)
{
    const float* query = (const float*)d_in[0];
    const float* key   = (const float*)d_in[1];
    const float* value = (const float*)d_in[2];
    // d_in[3] = mask (causal triu, fixed by problem definition) -> analytic
    const float* Wq = (const float*)d_in[4];
    const float* bq = (const float*)d_in[5];
    const float* Wk = (const float*)d_in[6];
    const float* bk = (const float*)d_in[7];
    const float* Wv = (const float*)d_in[8];
    const float* bv = (const float*)d_in[9];
    const float* Wo = (const float*)d_in[10];
    const float* bo = (const float*)d_in[11];
    float* out = (float*)d_out;

    float *pQ, *pK, *pV, *pA;
    float *prq, *prk, *prv, *prwq, *prwk, *prwv, *prwo;
    cudaGetSymbolAddress((void**)&pQ, g_Q);
    cudaGetSymbolAddress((void**)&pK, g_K);
    cudaGetSymbolAddress((void**)&pV, g_V);
    cudaGetSymbolAddress((void**)&pA, g_A);
    cudaGetSymbolAddress((void**)&prq, g_rq);
    cudaGetSymbolAddress((void**)&prk, g_rk);
    cudaGetSymbolAddress((void**)&prv, g_rv);
    cudaGetSymbolAddress((void**)&prwq, g_rwq);
    cudaGetSymbolAddress((void**)&prwk, g_rwk);
    cudaGetSymbolAddress((void**)&prwv, g_rwv);
    cudaGetSymbolAddress((void**)&prwo, g_rwo);

    cudaFuncSetAttribute(qkv_gemm_kernel,
                         cudaFuncAttributeMaxDynamicSharedMemorySize, GEMM_SMEM);
    cudaFuncSetAttribute(o_gemm_kernel,
                         cudaFuncAttributeMaxDynamicSharedMemorySize, GEMM_SMEM);
    cudaFuncSetAttribute(flash_mma_kernel,
                         cudaFuncAttributeMaxDynamicSharedMemorySize, FLASH_SMEM);

    // pre-round all GEMM inputs to tf32 (RNA) once
    const int NX4 = MROWS * DMODEL / 4;     // 1M float4
    const int NW4 = DMODEL * DMODEL / 4;    // 256K float4
    round_tf32_kernel<<<NX4 / 256, 256>>>((const float4*)query, (float4*)prq, NX4);
    round_tf32_kernel<<<NX4 / 256, 256>>>((const float4*)key,   (float4*)prk, NX4);
    round_tf32_kernel<<<NX4 / 256, 256>>>((const float4*)value, (float4*)prv, NX4);
    round_tf32_kernel<<<NW4 / 256, 256>>>((const float4*)Wq, (float4*)prwq, NW4);
    round_tf32_kernel<<<NW4 / 256, 256>>>((const float4*)Wk, (float4*)prwk, NW4);
    round_tf32_kernel<<<NW4 / 256, 256>>>((const float4*)Wv, (float4*)prwv, NW4);
    round_tf32_kernel<<<NW4 / 256, 256>>>((const float4*)Wo, (float4*)prwo, NW4);

    QKVArgs args;
    args.x[0] = prq;  args.x[1] = prk;  args.x[2] = prv;
    args.W[0] = prwq; args.W[1] = prwk; args.W[2] = prwv;
    args.b[0] = bq;   args.b[1] = bk;   args.b[2] = bv;
    args.out[0] = pQ; args.out[1] = pK; args.out[2] = pV;

    qkv_gemm_kernel<<<dim3(DMODEL / TBN, MROWS / TBM, 3), 256, GEMM_SMEM>>>(args);

    flash_mma_kernel<<<dim3(SEQ / FQ, BATCH * NHEAD), 256, FLASH_SMEM>>>(pQ, pK, pV, pA);

    o_gemm_kernel<<<dim3(DMODEL / TBN, MROWS / TBM), 256, GEMM_SMEM>>>(pA, prwo, bo, out);
}